// round 7
// baseline (speedup 1.0000x reference)
#include <cuda_runtime.h>
#include <cuda_fp16.h>
#include <math.h>
#include <stdint.h>

// ---------------- problem constants ----------------
#define NN       8192
#define D_IN     120
#define NODE_D   128
#define HID      64
#define NPW      17536     // num path weights
#define NB       336       // num bias
#define OUTD     60        // out is [N, 60, 60]

// scratch (device globals: allocation-free rule)
__device__ float  g_H[NN * HID];
__device__ float  g_G[NN * HID];
__device__ float  g_bias[NN * NB];
__device__ __half g_weight_h[(size_t)NN * NPW];
__device__ float  g_w3j[363];

// ---------------- Wigner 3j init (parallel, fp64, mirrors reference) ----------------
__device__ double dfac(int n) { double r = 1.0; for (int i = 2; i <= n; i++) r *= (double)i; return r; }
__device__ __forceinline__ int imax3(int a, int b, int c) { int m = a > b ? a : b; return m > c ? m : c; }
__device__ __forceinline__ int imin3(int a, int b, int c) { int m = a < b ? a : b; return m < c ? m : c; }

__constant__ int cL1[11]  = {0,1,2, 0,1,1,2, 0,1,2,2};
__constant__ int cL2[11]  = {0,1,2, 1,0,2,1, 2,1,0,2};
__constant__ int cLI[11]  = {0,0,0, 1,1,1,1, 2,2,2,2};
__constant__ int cOFF[11] = {0,1,10,35,44,53,98,143,168,213,238};
__constant__ int cCNT[11] = {1,9,25,9,9,45,45,25,45,25,125};
__constant__ int cUOFF[3] = {0,1,10};

__global__ void w3j_init_kernel() {
    __shared__ double Wc[363];
    __shared__ double sUr[35], sUi[35];
    int tid = threadIdx.x;

    if (tid < 3) {
        int l = tid, d = 2 * l + 1;
        double* Ur = sUr + cUOFF[l];
        double* Ui = sUi + cUOFF[l];
        for (int a = 0; a < d * d; a++) { Ur[a] = 0.0; Ui[a] = 0.0; }
        Ur[l * d + l] = 1.0;
        double s = 1.0 / sqrt(2.0);
        for (int m = 1; m <= l; m++) {
            double pm = ((m & 1) ? -1.0 : 1.0);
            Ur[(l + m) * d + (l + m)] = pm * s;
            Ur[(l + m) * d + (l - m)] = s;
            Ui[(l - m) * d + (l - m)] = s;
            Ui[(l - m) * d + (l + m)] = -pm * s;
        }
    }
    __syncthreads();

    if (tid < 363) {
        int e = tid;
        int p = 0;
        while (p < 10 && e >= cOFF[p] + cCNT[p]) p++;
        int le = e - cOFF[p];
        int j1 = cL1[p], j2 = cL2[p], j3 = cLI[p];
        int d2 = 2 * j2 + 1, d3 = 2 * j3 + 1;
        int c = le % d3, b = (le / d3) % d2, a = le / (d3 * d2);
        int m1 = a - j1, m2 = b - j2, m3 = c - j3;
        double val = 0.0;
        if (m1 + m2 + m3 == 0) {
            double tri = dfac(j1 + j2 - j3) * dfac(j1 - j2 + j3) * dfac(-j1 + j2 + j3)
                       / dfac(j1 + j2 + j3 + 1);
            double pref = sqrt(tri * dfac(j1 + m1) * dfac(j1 - m1) * dfac(j2 + m2)
                               * dfac(j2 - m2) * dfac(j3 + m3) * dfac(j3 - m3));
            int t0 = imax3(0, j2 - j3 - m1, j1 - j3 + m2);
            int t1 = imin3(j1 + j2 - j3, j1 - m1, j2 + m2);
            double s = 0.0;
            for (int t = t0; t <= t1; t++) {
                double den = dfac(t) * dfac(j1 + j2 - j3 - t) * dfac(j1 - m1 - t)
                           * dfac(j2 + m2 - t) * dfac(j3 - j2 + m1 + t) * dfac(j3 - j1 - m2 + t);
                s += ((t & 1) ? -1.0 : 1.0) / den;
            }
            double sign = (((j1 - j2 - m3) & 1) ? -1.0 : 1.0);
            val = sign * pref * s;
        }
        Wc[e] = val;
    }
    __syncthreads();

    if (tid < 363) {
        int e = tid;
        int p = 0;
        while (p < 10 && e >= cOFF[p] + cCNT[p]) p++;
        int le = e - cOFF[p];
        int j1 = cL1[p], j2 = cL2[p], j3 = cLI[p];
        int d1 = 2 * j1 + 1, d2 = 2 * j2 + 1, d3 = 2 * j3 + 1;
        int k = le % d3, j = (le / d3) % d2, i = le / (d3 * d2);
        const double* U1r = sUr + cUOFF[j1]; const double* U1i = sUi + cUOFF[j1];
        const double* U2r = sUr + cUOFF[j2]; const double* U2i = sUi + cUOFF[j2];
        const double* U3r = sUr + cUOFF[j3]; const double* U3i = sUi + cUOFF[j3];
        const double* Wp = Wc + cOFF[p];
        double re = 0.0;
        for (int m = 0; m < d1; m++) {
            double u1r = U1r[i * d1 + m], u1i = U1i[i * d1 + m];
            if (u1r == 0.0 && u1i == 0.0) continue;
            for (int nn = 0; nn < d2; nn++) {
                double u2r = U2r[j * d2 + nn], u2i = U2i[j * d2 + nn];
                if (u2r == 0.0 && u2i == 0.0) continue;
                double ar = u1r * u2r - u1i * u2i;
                double ai = u1r * u2i + u1i * u2r;
                for (int pp = 0; pp < d3; pp++) {
                    double w = Wp[(m * d2 + nn) * d3 + pp];
                    if (w == 0.0) continue;
                    re += (ar * U3r[k * d3 + pp] - ai * U3i[k * d3 + pp]) * w;
                }
            }
        }
        g_w3j[e] = (float)re;
    }
}

// ---------------- hidden layers: 8 nodes per block ----------------
#define HNODES 8
__global__ __launch_bounds__(128) void hidden_kernel(
    const float* __restrict__ embed,
    const float* __restrict__ w1w, const float* __restrict__ b1w,
    const float* __restrict__ w1b, const float* __restrict__ b1b) {
    __shared__ float se[HNODES][NODE_D];
    int n0 = blockIdx.x * HNODES, tid = threadIdx.x;
    #pragma unroll
    for (int it = 0; it < HNODES; it++) {
        int i = tid + it * 128;
        se[i >> 7][i & 127] = embed[(n0 + (i >> 7)) * NODE_D + (i & 127)];
    }
    __syncthreads();
    int t = tid & 63;
    const float* wmat = (tid < 64) ? w1w : w1b;
    const float* bvec = (tid < 64) ? b1w : b1b;
    float* gout = (tid < 64) ? g_H : g_G;
    float b = bvec[t];
    float acc[HNODES];
    #pragma unroll
    for (int n = 0; n < HNODES; n++) acc[n] = b;
    #pragma unroll 4
    for (int h = 0; h < NODE_D; h++) {
        float w = wmat[h * HID + t];
        #pragma unroll
        for (int n = 0; n < HNODES; n++) acc[n] += se[n][h] * w;
    }
    #pragma unroll
    for (int n = 0; n < HNODES; n++) {
        float a = acc[n];
        gout[(n0 + n) * HID + t] = a / (1.0f + expf(-a));
    }
}

// ---------------- bias: 8 nodes per block ----------------
#define BNODES 8
__global__ __launch_bounds__(352) void bias_kernel(
    const float* __restrict__ w2b, const float* __restrict__ b2b) {
    __shared__ float sg[BNODES][HID];
    int n0 = blockIdx.x * BNODES, tid = threadIdx.x;
    for (int i = tid; i < BNODES * HID; i += 352)
        sg[i >> 6][i & 63] = g_G[(n0 + (i >> 6)) * HID + (i & 63)];
    __syncthreads();
    if (tid < NB) {
        float b = b2b[tid];
        float acc[BNODES];
        #pragma unroll
        for (int n = 0; n < BNODES; n++) acc[n] = b;
        #pragma unroll 4
        for (int h = 0; h < HID; h++) {
            float w = w2b[h * NB + tid];
            #pragma unroll
            for (int n = 0; n < BNODES; n++) acc[n] += sg[n][h] * w;
        }
        #pragma unroll
        for (int n = 0; n < BNODES; n++) g_bias[(n0 + n) * NB + tid] = acc[n];
    }
}

// ---------------- tf32 mma.sync GEMM with frag-major smem ----------------
// CTA tile 128x128, K=64. 8 warps (4x2), warp tile 32x64, m16n8k8 tf32.
// A2[wr=4][k0=8][lane=32][12] (12-word padded rows, 8 used) = 49152 B
// B2[wc=2][k0=8][lane=32][20] (20-word padded rows, 16 used) = 40960 B
#define G_A2   0
#define G_B2   49152
#define G_BIAS 90112
#define G_TOT  90624

__device__ __forceinline__ uint32_t f2tf32(float x) {
    uint32_t r;
    asm("cvt.rna.tf32.f32 %0, %1;" : "=r"(r) : "f"(x));
    return r;
}

__global__ __launch_bounds__(256, 2) void gemm_mma_kernel(
    const float* __restrict__ w2w, const float* __restrict__ b2w) {
    extern __shared__ char smem[];
    uint32_t* A2 = (uint32_t*)(smem + G_A2);
    uint32_t* B2 = (uint32_t*)(smem + G_B2);
    float* bsm = (float*)(smem + G_BIAS);

    int tid = threadIdx.x;
    int wid = tid >> 5, lane = tid & 31;
    int m0 = blockIdx.y * 128;
    int n0 = blockIdx.x * 128;

    if (tid < 128) bsm[tid] = b2w[n0 + tid];

    // stage A into fragment-major layout
    #pragma unroll
    for (int it = 0; it < 8; it++) {
        int i = tid + it * 256;             // 0..2047
        int m = i >> 4, k4 = (i & 15) * 4;
        float4 v = *(const float4*)&g_H[(m0 + m) * HID + k4];
        int wr = m >> 5, ml = m & 31, mi = ml >> 4, r16 = ml & 15;
        int half = r16 >> 3, lr = r16 & 7;
        int k0 = k4 >> 3, khalf = (k4 & 7) >> 2;
        int reg = mi * 4 + khalf * 2 + half;
        uint32_t base = (uint32_t)(((wr * 8 + k0) * 32 + lr * 4) * 12 + reg);
        A2[base + 0 * 12] = f2tf32(v.x);
        A2[base + 1 * 12] = f2tf32(v.y);
        A2[base + 2 * 12] = f2tf32(v.z);
        A2[base + 3 * 12] = f2tf32(v.w);
    }
    // stage B into fragment-major layout
    #pragma unroll
    for (int it = 0; it < 8; it++) {
        int i = tid + it * 256;
        int k = i >> 5, n4 = (i & 31) * 4;
        float4 v = *(const float4*)&w2w[k * NPW + n0 + n4];
        int wc = n4 >> 6, nl = n4 & 63, f = nl >> 3, lrb = nl & 7;
        int k0 = k >> 3, j = (k & 7) >> 2, lc = k & 3;
        int reg = f * 2 + j;
        uint32_t base = (uint32_t)(((wc * 8 + k0) * 32) * 20 + reg);
        B2[base + ((lrb + 0) * 4 + lc) * 20] = f2tf32(v.x);
        B2[base + ((lrb + 1) * 4 + lc) * 20] = f2tf32(v.y);
        B2[base + ((lrb + 2) * 4 + lc) * 20] = f2tf32(v.z);
        B2[base + ((lrb + 3) * 4 + lc) * 20] = f2tf32(v.w);
    }
    __syncthreads();

    int wm_idx = wid >> 1, wc_idx = wid & 1;
    int wm = wm_idx * 32, wn = wc_idx * 64;
    int lr = lane >> 2, lc = lane & 3;

    float acc[2][8][4];
    #pragma unroll
    for (int mi = 0; mi < 2; mi++)
        #pragma unroll
        for (int f = 0; f < 8; f++)
            #pragma unroll
            for (int c = 0; c < 4; c++) acc[mi][f][c] = 0.0f;

    const uint32_t* Abase = &A2[((wm_idx * 8) * 32 + lane) * 12];
    const uint32_t* Bbase = &B2[((wc_idx * 8) * 32 + lane) * 20];

    #pragma unroll
    for (int k0 = 0; k0 < 8; k0++) {
        uint4 af0 = *(const uint4*)&Abase[k0 * 384];       // mi=0: a0,a1,a2,a3
        uint4 af1 = *(const uint4*)&Abase[k0 * 384 + 4];   // mi=1
        uint4 bq0 = *(const uint4*)&Bbase[k0 * 640];
        uint4 bq1 = *(const uint4*)&Bbase[k0 * 640 + 4];
        uint4 bq2 = *(const uint4*)&Bbase[k0 * 640 + 8];
        uint4 bq3 = *(const uint4*)&Bbase[k0 * 640 + 12];
        uint32_t br[16] = {bq0.x, bq0.y, bq0.z, bq0.w, bq1.x, bq1.y, bq1.z, bq1.w,
                           bq2.x, bq2.y, bq2.z, bq2.w, bq3.x, bq3.y, bq3.z, bq3.w};
        #pragma unroll
        for (int f = 0; f < 8; f++) {
            asm volatile(
                "mma.sync.aligned.m16n8k8.row.col.f32.tf32.tf32.f32 "
                "{%0,%1,%2,%3}, {%4,%5,%6,%7}, {%8,%9}, {%0,%1,%2,%3};"
                : "+f"(acc[0][f][0]), "+f"(acc[0][f][1]),
                  "+f"(acc[0][f][2]), "+f"(acc[0][f][3])
                : "r"(af0.x), "r"(af0.y), "r"(af0.z), "r"(af0.w),
                  "r"(br[2 * f]), "r"(br[2 * f + 1]));
        }
        #pragma unroll
        for (int f = 0; f < 8; f++) {
            asm volatile(
                "mma.sync.aligned.m16n8k8.row.col.f32.tf32.tf32.f32 "
                "{%0,%1,%2,%3}, {%4,%5,%6,%7}, {%8,%9}, {%0,%1,%2,%3};"
                : "+f"(acc[1][f][0]), "+f"(acc[1][f][1]),
                  "+f"(acc[1][f][2]), "+f"(acc[1][f][3])
                : "r"(af1.x), "r"(af1.y), "r"(af1.z), "r"(af1.w),
                  "r"(br[2 * f]), "r"(br[2 * f + 1]));
        }
    }

    // epilogue: bias add, fp16 convert, half2 stores
    #pragma unroll
    for (int mi = 0; mi < 2; mi++) {
        int r = m0 + wm + mi * 16 + lr;
        #pragma unroll
        for (int f = 0; f < 8; f++) {
            int col = wn + f * 8 + 2 * lc;
            float b0 = bsm[col], b1 = bsm[col + 1];
            *(__half2*)&g_weight_h[(size_t)r * NPW + n0 + col] =
                __floats2half2_rn(acc[mi][f][0] + b0, acc[mi][f][1] + b1);
            *(__half2*)&g_weight_h[(size_t)(r + 8) * NPW + n0 + col] =
                __floats2half2_rn(acc[mi][f][2] + b0, acc[mi][f][3] + b1);
        }
    }
}

// ---------------- per-node expansion (weights staged in smem) ----------------
template<int MUL_IN, int MUL1, int MUL2, int D1, int D2, int DI,
         int W_OFF, int B_OFF, int W3J_OFF, int ROW_OFF, int COL_OFF, int X_OFF, bool ACCUM>
__device__ __forceinline__ void path_fn(int lid, const __half* wsm,
                                        const float* xsh, const float* bsh,
                                        const float* w3s, float* osh) {
    constexpr int UV = MUL1 * MUL2;
    int u = lid / MUL2, v = lid % MUL2;
    float res[DI];
    #pragma unroll
    for (int k = 0; k < DI; k++) res[k] = 0.0f;
    const __half* wp = wsm + W_OFF + lid;
    #pragma unroll
    for (int w = 0; w < MUL_IN; w++) {
        float wt = __half2float(wp[w * UV]);
        #pragma unroll
        for (int k = 0; k < DI; k++) res[k] += wt * xsh[X_OFF + w * DI + k];
    }
    if (B_OFF >= 0) res[0] += bsh[B_OFF + lid];
    constexpr float inv = 1.0f / (float)MUL_IN;
    #pragma unroll
    for (int a = 0; a < D1; a++) {
        #pragma unroll
        for (int b = 0; b < D2; b++) {
            float acc = 0.0f;
            #pragma unroll
            for (int k = 0; k < DI; k++)
                acc += w3s[W3J_OFF + (a * D2 + b) * DI + k] * res[k];
            float* o = &osh[(ROW_OFF + u * D1 + a) * OUTD + COL_OFF + v * D2 + b];
            if (ACCUM) *o += acc * inv;
            else       *o  = acc * inv;
        }
    }
}

#define ETHREADS 512
#define E_WSM_BYTES (NPW * 2)   // 35072
__global__ __launch_bounds__(ETHREADS) void expand_kernel(
    const float* __restrict__ x_in, float* __restrict__ out) {
    extern __shared__ char esm[];
    __half* wsm = (__half*)esm;
    __shared__ float xsh[D_IN];
    __shared__ float bsh[NB];
    __shared__ float w3s[363];
    __shared__ float osh[OUTD * OUTD];
    int n = blockIdx.x, tid = threadIdx.x;
    const float4* wrow4 = (const float4*)(g_weight_h + (size_t)n * NPW);

    for (int i = tid; i < NPW / 8; i += ETHREADS) ((float4*)wsm)[i] = wrow4[i];
    for (int i = tid; i < D_IN; i += ETHREADS) xsh[i] = x_in[n * D_IN + i];
    for (int i = tid; i < NB; i += ETHREADS) bsh[i] = g_bias[n * NB + i];
    for (int i = tid; i < 363; i += ETHREADS) w3s[i] = g_w3j[i];
    for (int i = tid; i < OUTD * OUTD; i += ETHREADS) osh[i] = 0.0f;
    __syncthreads();

    // Wave 1 (large paths)
    //         MUL_IN MUL1 MUL2 D1 D2 DI  W_OFF  B_OFF W3J ROW COL X_OFF ACC
    if (tid < 256) {
        path_fn<32, 16, 16, 1, 1, 1,     0,   0,   0,   0,  0,  0, false>(tid,       wsm, xsh, bsh, w3s, osh);
    } else if (tid < 384) {
        path_fn<16, 16,  8, 1, 3, 3, 10752,  -1,  35,   0, 16, 32, false>(tid - 256, wsm, xsh, bsh, w3s, osh);
    } else {
        path_fn<16,  8, 16, 3, 1, 3, 12800,  -1,  44,  16,  0, 32, false>(tid - 384, wsm, xsh, bsh, w3s, osh);
    }

    // Wave 2 (small paths): disjoint osh elements
    if (tid < 64) {
        path_fn<32,  8,  8, 3, 3, 1,  8192, 256,   1,  16, 16,  0, false>(tid,       wsm, xsh, bsh, w3s, osh);
        path_fn< 8,  8,  8, 3, 3, 5, 16384,  -1, 168,  16, 16, 80, true >(tid,       wsm, xsh, bsh, w3s, osh);
    } else if (tid < 128) {
        path_fn< 8, 16,  4, 1, 5, 5, 15872,  -1, 143,   0, 40, 80, false>(tid - 64,  wsm, xsh, bsh, w3s, osh);
    } else if (tid < 192) {
        path_fn< 8,  4, 16, 5, 1, 5, 16896,  -1, 213,  40,  0, 80, false>(tid - 128, wsm, xsh, bsh, w3s, osh);
    } else if (tid < 224) {
        path_fn<16,  8,  4, 3, 5, 3, 14848,  -1,  53,  16, 40, 32, false>(tid - 192, wsm, xsh, bsh, w3s, osh);
    } else if (tid < 256) {
        path_fn<16,  4,  8, 5, 3, 3, 15360,  -1,  98,  40, 16, 32, false>(tid - 224, wsm, xsh, bsh, w3s, osh);
    } else if (tid < 272) {
        path_fn<32,  4,  4, 5, 5, 1, 10240, 320,  10,  40, 40,  0, false>(tid - 256, wsm, xsh, bsh, w3s, osh);
        path_fn< 8,  4,  4, 5, 5, 5, 17408,  -1, 238,  40, 40, 80, true >(tid - 256, wsm, xsh, bsh, w3s, osh);
    }
    __syncthreads();

    for (int i = tid; i < OUTD * OUTD; i += ETHREADS)
        out[(size_t)n * (OUTD * OUTD) + i] = osh[i];
}

// ---------------- launch ----------------
extern "C" void kernel_launch(void* const* d_in, const int* in_sizes, int n_in,
                              void* d_out, int out_size) {
    const float* x_in  = (const float*)d_in[0];
    const float* embed = (const float*)d_in[1];
    const float* w1w   = (const float*)d_in[2];
    const float* b1w   = (const float*)d_in[3];
    const float* w2w   = (const float*)d_in[4];
    const float* b2w   = (const float*)d_in[5];
    const float* w1b   = (const float*)d_in[6];
    const float* b1b   = (const float*)d_in[7];
    const float* w2b   = (const float*)d_in[8];
    const float* b2b   = (const float*)d_in[9];
    float* out = (float*)d_out;

    cudaFuncSetAttribute(gemm_mma_kernel, cudaFuncAttributeMaxDynamicSharedMemorySize, G_TOT);
    cudaFuncSetAttribute(expand_kernel, cudaFuncAttributeMaxDynamicSharedMemorySize, E_WSM_BYTES);

    w3j_init_kernel<<<1, 384>>>();
    hidden_kernel<<<NN / HNODES, 128>>>(embed, w1w, b1w, w1b, b1b);
    bias_kernel<<<NN / BNODES, 352>>>(w2b, b2b);
    gemm_mma_kernel<<<dim3(NPW / 128, NN / 128), 256, G_TOT>>>(w2w, b2w);
    expand_kernel<<<NN, ETHREADS, E_WSM_BYTES>>>(x_in, out);
}

// round 8
// speedup vs baseline: 1.2871x; 1.2871x over previous
#include <cuda_runtime.h>
#include <cuda_fp16.h>
#include <math.h>
#include <stdint.h>

// ---------------- problem constants ----------------
#define NN       8192
#define D_IN     120
#define NODE_D   128
#define HID      64
#define NPW      17536     // num path weights
#define NB       336       // num bias
#define OUTD     60        // out is [N, 60, 60]

// scratch (device globals: allocation-free rule)
__device__ float  g_H[NN * HID];
__device__ float  g_G[NN * HID];
__device__ float  g_bias[NN * NB];
__device__ __half g_weight_h[(size_t)NN * NPW];
__device__ float  g_w3j[363];

// ---------------- Wigner 3j init (parallel, fp64, mirrors reference) ----------------
__device__ double dfac(int n) { double r = 1.0; for (int i = 2; i <= n; i++) r *= (double)i; return r; }
__device__ __forceinline__ int imax3(int a, int b, int c) { int m = a > b ? a : b; return m > c ? m : c; }
__device__ __forceinline__ int imin3(int a, int b, int c) { int m = a < b ? a : b; return m < c ? m : c; }

__constant__ int cL1[11]  = {0,1,2, 0,1,1,2, 0,1,2,2};
__constant__ int cL2[11]  = {0,1,2, 1,0,2,1, 2,1,0,2};
__constant__ int cLI[11]  = {0,0,0, 1,1,1,1, 2,2,2,2};
__constant__ int cOFF[11] = {0,1,10,35,44,53,98,143,168,213,238};
__constant__ int cCNT[11] = {1,9,25,9,9,45,45,25,45,25,125};
__constant__ int cUOFF[3] = {0,1,10};

__global__ void w3j_init_kernel() {
    __shared__ double Wc[363];
    __shared__ double sUr[35], sUi[35];
    int tid = threadIdx.x;

    if (tid < 3) {
        int l = tid, d = 2 * l + 1;
        double* Ur = sUr + cUOFF[l];
        double* Ui = sUi + cUOFF[l];
        for (int a = 0; a < d * d; a++) { Ur[a] = 0.0; Ui[a] = 0.0; }
        Ur[l * d + l] = 1.0;
        double s = 1.0 / sqrt(2.0);
        for (int m = 1; m <= l; m++) {
            double pm = ((m & 1) ? -1.0 : 1.0);
            Ur[(l + m) * d + (l + m)] = pm * s;
            Ur[(l + m) * d + (l - m)] = s;
            Ui[(l - m) * d + (l - m)] = s;
            Ui[(l - m) * d + (l + m)] = -pm * s;
        }
    }
    __syncthreads();

    if (tid < 363) {
        int e = tid;
        int p = 0;
        while (p < 10 && e >= cOFF[p] + cCNT[p]) p++;
        int le = e - cOFF[p];
        int j1 = cL1[p], j2 = cL2[p], j3 = cLI[p];
        int d2 = 2 * j2 + 1, d3 = 2 * j3 + 1;
        int c = le % d3, b = (le / d3) % d2, a = le / (d3 * d2);
        int m1 = a - j1, m2 = b - j2, m3 = c - j3;
        double val = 0.0;
        if (m1 + m2 + m3 == 0) {
            double tri = dfac(j1 + j2 - j3) * dfac(j1 - j2 + j3) * dfac(-j1 + j2 + j3)
                       / dfac(j1 + j2 + j3 + 1);
            double pref = sqrt(tri * dfac(j1 + m1) * dfac(j1 - m1) * dfac(j2 + m2)
                               * dfac(j2 - m2) * dfac(j3 + m3) * dfac(j3 - m3));
            int t0 = imax3(0, j2 - j3 - m1, j1 - j3 + m2);
            int t1 = imin3(j1 + j2 - j3, j1 - m1, j2 + m2);
            double s = 0.0;
            for (int t = t0; t <= t1; t++) {
                double den = dfac(t) * dfac(j1 + j2 - j3 - t) * dfac(j1 - m1 - t)
                           * dfac(j2 + m2 - t) * dfac(j3 - j2 + m1 + t) * dfac(j3 - j1 - m2 + t);
                s += ((t & 1) ? -1.0 : 1.0) / den;
            }
            double sign = (((j1 - j2 - m3) & 1) ? -1.0 : 1.0);
            val = sign * pref * s;
        }
        Wc[e] = val;
    }
    __syncthreads();

    if (tid < 363) {
        int e = tid;
        int p = 0;
        while (p < 10 && e >= cOFF[p] + cCNT[p]) p++;
        int le = e - cOFF[p];
        int j1 = cL1[p], j2 = cL2[p], j3 = cLI[p];
        int d1 = 2 * j1 + 1, d2 = 2 * j2 + 1, d3 = 2 * j3 + 1;
        int k = le % d3, j = (le / d3) % d2, i = le / (d3 * d2);
        const double* U1r = sUr + cUOFF[j1]; const double* U1i = sUi + cUOFF[j1];
        const double* U2r = sUr + cUOFF[j2]; const double* U2i = sUi + cUOFF[j2];
        const double* U3r = sUr + cUOFF[j3]; const double* U3i = sUi + cUOFF[j3];
        const double* Wp = Wc + cOFF[p];
        double re = 0.0;
        for (int m = 0; m < d1; m++) {
            double u1r = U1r[i * d1 + m], u1i = U1i[i * d1 + m];
            if (u1r == 0.0 && u1i == 0.0) continue;
            for (int nn = 0; nn < d2; nn++) {
                double u2r = U2r[j * d2 + nn], u2i = U2i[j * d2 + nn];
                if (u2r == 0.0 && u2i == 0.0) continue;
                double ar = u1r * u2r - u1i * u2i;
                double ai = u1r * u2i + u1i * u2r;
                for (int pp = 0; pp < d3; pp++) {
                    double w = Wp[(m * d2 + nn) * d3 + pp];
                    if (w == 0.0) continue;
                    re += (ar * U3r[k * d3 + pp] - ai * U3i[k * d3 + pp]) * w;
                }
            }
        }
        g_w3j[e] = (float)re;
    }
}

// ---------------- hidden layers: 8 nodes per block ----------------
#define HNODES 8
__global__ __launch_bounds__(128) void hidden_kernel(
    const float* __restrict__ embed,
    const float* __restrict__ w1w, const float* __restrict__ b1w,
    const float* __restrict__ w1b, const float* __restrict__ b1b) {
    __shared__ float se[HNODES][NODE_D];
    int n0 = blockIdx.x * HNODES, tid = threadIdx.x;
    #pragma unroll
    for (int it = 0; it < HNODES; it++) {
        int i = tid + it * 128;
        se[i >> 7][i & 127] = embed[(n0 + (i >> 7)) * NODE_D + (i & 127)];
    }
    __syncthreads();
    int t = tid & 63;
    const float* wmat = (tid < 64) ? w1w : w1b;
    const float* bvec = (tid < 64) ? b1w : b1b;
    float* gout = (tid < 64) ? g_H : g_G;
    float b = bvec[t];
    float acc[HNODES];
    #pragma unroll
    for (int n = 0; n < HNODES; n++) acc[n] = b;
    #pragma unroll 4
    for (int h = 0; h < NODE_D; h++) {
        float w = wmat[h * HID + t];
        #pragma unroll
        for (int n = 0; n < HNODES; n++) acc[n] += se[n][h] * w;
    }
    #pragma unroll
    for (int n = 0; n < HNODES; n++) {
        float a = acc[n];
        gout[(n0 + n) * HID + t] = a / (1.0f + expf(-a));
    }
}

// ---------------- bias: 8 nodes per block ----------------
#define BNODES 8
__global__ __launch_bounds__(352) void bias_kernel(
    const float* __restrict__ w2b, const float* __restrict__ b2b) {
    __shared__ float sg[BNODES][HID];
    int n0 = blockIdx.x * BNODES, tid = threadIdx.x;
    for (int i = tid; i < BNODES * HID; i += 352)
        sg[i >> 6][i & 63] = g_G[(n0 + (i >> 6)) * HID + (i & 63)];
    __syncthreads();
    if (tid < NB) {
        float b = b2b[tid];
        float acc[BNODES];
        #pragma unroll
        for (int n = 0; n < BNODES; n++) acc[n] = b;
        #pragma unroll 4
        for (int h = 0; h < HID; h++) {
            float w = w2b[h * NB + tid];
            #pragma unroll
            for (int n = 0; n < BNODES; n++) acc[n] += sg[n][h] * w;
        }
        #pragma unroll
        for (int n = 0; n < BNODES; n++) g_bias[(n0 + n) * NB + tid] = acc[n];
    }
}

// ---------------- tf32 mma.sync GEMM (R6 mainloop + coalesced epilogue) ----------------
// CTA tile 128x128, K=64 staged once in smem as tf32. 256 threads = 8 warps (4x2),
// each warp computes 32x64 via m16n8k8 tf32 mma.sync.
// Epilogue: accums staged to smem (reusing As region) then coalesced uint4 stores.
#define SA 68    // As [m][k] stride (floats)
#define SB 136   // Bs [k][n] stride (floats)
#define GM_SMEM_A 0
#define GM_SMEM_B (128 * SA * 4)                 // 34816
#define GM_SMEM_BIAS (GM_SMEM_B + 64 * SB * 4)   // 69632
#define GM_SMEM_TOT (GM_SMEM_BIAS + 512)         // 70144
// epilogue staging reuses [0, 34816): 128 rows x 68 half2 (=136 half) per row

__device__ __forceinline__ uint32_t f2tf32(float x) {
    uint32_t r;
    asm("cvt.rna.tf32.f32 %0, %1;" : "=r"(r) : "f"(x));
    return r;
}

__global__ __launch_bounds__(256, 2) void gemm_mma_kernel(
    const float* __restrict__ w2w, const float* __restrict__ b2w) {
    extern __shared__ char smem[];
    float* As = (float*)(smem + GM_SMEM_A);
    float* Bs = (float*)(smem + GM_SMEM_B);
    float* bsm = (float*)(smem + GM_SMEM_BIAS);
    const uint32_t* Asu = (const uint32_t*)As;
    const uint32_t* Bsu = (const uint32_t*)Bs;

    int tid = threadIdx.x;
    int wid = tid >> 5, lane = tid & 31;
    int m0 = blockIdx.y * 128;
    int n0 = blockIdx.x * 128;

    if (tid < 128) bsm[tid] = b2w[n0 + tid];

    // stage A (g_H[m0..m0+127][0..63]) as tf32, [m][k] stride SA
    #pragma unroll
    for (int it = 0; it < 8; it++) {
        int i = tid + it * 256;
        int m = i >> 4, k4 = (i & 15) * 4;
        float4 v = *(const float4*)&g_H[(m0 + m) * HID + k4];
        uint32_t* d = (uint32_t*)&As[m * SA + k4];
        d[0] = f2tf32(v.x); d[1] = f2tf32(v.y); d[2] = f2tf32(v.z); d[3] = f2tf32(v.w);
    }
    // stage B (w2w[0..63][n0..n0+127]) as tf32, [k][n] stride SB
    #pragma unroll
    for (int it = 0; it < 8; it++) {
        int i = tid + it * 256;
        int k = i >> 5, n4 = (i & 31) * 4;
        float4 v = *(const float4*)&w2w[k * NPW + n0 + n4];
        uint32_t* d = (uint32_t*)&Bs[k * SB + n4];
        d[0] = f2tf32(v.x); d[1] = f2tf32(v.y); d[2] = f2tf32(v.z); d[3] = f2tf32(v.w);
    }
    __syncthreads();

    int wm = (wid >> 1) * 32;
    int wn = (wid & 1) * 64;
    int lr = lane >> 2;
    int lc = lane & 3;

    float acc[2][8][4];
    #pragma unroll
    for (int mi = 0; mi < 2; mi++)
        #pragma unroll
        for (int f = 0; f < 8; f++)
            #pragma unroll
            for (int c = 0; c < 4; c++) acc[mi][f][c] = 0.0f;

    #pragma unroll
    for (int k0 = 0; k0 < HID; k0 += 8) {
        uint32_t bf[8][2];
        #pragma unroll
        for (int f = 0; f < 8; f++) {
            int n = wn + f * 8 + lr;
            bf[f][0] = Bsu[(k0 + lc) * SB + n];
            bf[f][1] = Bsu[(k0 + 4 + lc) * SB + n];
        }
        #pragma unroll
        for (int mi = 0; mi < 2; mi++) {
            int r = wm + mi * 16 + lr;
            uint32_t a0 = Asu[r * SA + k0 + lc];
            uint32_t a1 = Asu[(r + 8) * SA + k0 + lc];
            uint32_t a2 = Asu[r * SA + k0 + 4 + lc];
            uint32_t a3 = Asu[(r + 8) * SA + k0 + 4 + lc];
            #pragma unroll
            for (int f = 0; f < 8; f++) {
                asm volatile(
                    "mma.sync.aligned.m16n8k8.row.col.f32.tf32.tf32.f32 "
                    "{%0,%1,%2,%3}, {%4,%5,%6,%7}, {%8,%9}, {%0,%1,%2,%3};"
                    : "+f"(acc[mi][f][0]), "+f"(acc[mi][f][1]),
                      "+f"(acc[mi][f][2]), "+f"(acc[mi][f][3])
                    : "r"(a0), "r"(a1), "r"(a2), "r"(a3),
                      "r"(bf[f][0]), "r"(bf[f][1]));
            }
        }
    }

    // ---- epilogue: bias add -> smem stage (half2) -> coalesced uint4 stores ----
    __syncthreads();   // done reading As/Bs; reuse As region as staging
    __half2* stg2 = (__half2*)smem;    // [128 rows][68 half2] (64 used)
    #pragma unroll
    for (int mi = 0; mi < 2; mi++) {
        int r = wm + mi * 16 + lr;
        #pragma unroll
        for (int f = 0; f < 8; f++) {
            int col = wn + f * 8 + 2 * lc;
            float b0 = bsm[col], b1 = bsm[col + 1];
            int c2 = (col >> 1);
            stg2[r * 68 + c2]       = __floats2half2_rn(acc[mi][f][0] + b0, acc[mi][f][1] + b1);
            stg2[(r + 8) * 68 + c2] = __floats2half2_rn(acc[mi][f][2] + b0, acc[mi][f][3] + b1);
        }
    }
    __syncthreads();
    const __half* stg = (const __half*)smem;
    #pragma unroll
    for (int it = 0; it < 8; it++) {
        int i = tid + it * 256;            // 0..2047
        int r = i >> 4, q = i & 15;        // row, uint4 index (16 per row)
        uint4 v = *(const uint4*)&stg[r * 136 + q * 8];
        *(uint4*)&g_weight_h[(size_t)(m0 + r) * NPW + n0 + q * 8] = v;
    }
}

// ---------------- per-node expansion (direct gmem weight reads, R6 style) ----------------
template<int MUL_IN, int MUL1, int MUL2, int D1, int D2, int DI,
         int W_OFF, int B_OFF, int W3J_OFF, int ROW_OFF, int COL_OFF, int X_OFF, bool ACCUM>
__device__ __forceinline__ void path_fn(int lid, const __half* __restrict__ wrow,
                                        const float* xsh, const float* bsh,
                                        const float* w3s, float* osh) {
    constexpr int UV = MUL1 * MUL2;
    int u = lid / MUL2, v = lid % MUL2;
    float res[DI];
    #pragma unroll
    for (int k = 0; k < DI; k++) res[k] = 0.0f;
    const __half* wp = wrow + W_OFF + lid;
    #pragma unroll
    for (int w = 0; w < MUL_IN; w++) {
        float wt = __half2float(wp[w * UV]);
        #pragma unroll
        for (int k = 0; k < DI; k++) res[k] += wt * xsh[X_OFF + w * DI + k];
    }
    if (B_OFF >= 0) res[0] += bsh[B_OFF + lid];
    constexpr float inv = 1.0f / (float)MUL_IN;
    #pragma unroll
    for (int a = 0; a < D1; a++) {
        #pragma unroll
        for (int b = 0; b < D2; b++) {
            float acc = 0.0f;
            #pragma unroll
            for (int k = 0; k < DI; k++)
                acc += w3s[W3J_OFF + (a * D2 + b) * DI + k] * res[k];
            float* o = &osh[(ROW_OFF + u * D1 + a) * OUTD + COL_OFF + v * D2 + b];
            if (ACCUM) *o += acc * inv;
            else       *o  = acc * inv;
        }
    }
}

#define ETHREADS 512
__global__ __launch_bounds__(ETHREADS) void expand_kernel(
    const float* __restrict__ x_in, float* __restrict__ out) {
    __shared__ float xsh[D_IN];
    __shared__ float bsh[NB];
    __shared__ float w3s[363];
    __shared__ float osh[OUTD * OUTD];
    int n = blockIdx.x, tid = threadIdx.x;
    const __half* wrow = g_weight_h + (size_t)n * NPW;

    for (int i = tid; i < D_IN; i += ETHREADS) xsh[i] = x_in[n * D_IN + i];
    for (int i = tid; i < NB; i += ETHREADS) bsh[i] = g_bias[n * NB + i];
    for (int i = tid; i < 363; i += ETHREADS) w3s[i] = g_w3j[i];
    for (int i = tid; i < OUTD * OUTD; i += ETHREADS) osh[i] = 0.0f;
    __syncthreads();

    // Wave 1 (large paths)
    //         MUL_IN MUL1 MUL2 D1 D2 DI  W_OFF  B_OFF W3J ROW COL X_OFF ACC
    if (tid < 256) {
        path_fn<32, 16, 16, 1, 1, 1,     0,   0,   0,   0,  0,  0, false>(tid,       wrow, xsh, bsh, w3s, osh);
    } else if (tid < 384) {
        path_fn<16, 16,  8, 1, 3, 3, 10752,  -1,  35,   0, 16, 32, false>(tid - 256, wrow, xsh, bsh, w3s, osh);
    } else {
        path_fn<16,  8, 16, 3, 1, 3, 12800,  -1,  44,  16,  0, 32, false>(tid - 384, wrow, xsh, bsh, w3s, osh);
    }

    // Wave 2 (small paths): disjoint osh elements
    if (tid < 64) {
        path_fn<32,  8,  8, 3, 3, 1,  8192, 256,   1,  16, 16,  0, false>(tid,       wrow, xsh, bsh, w3s, osh);
        path_fn< 8,  8,  8, 3, 3, 5, 16384,  -1, 168,  16, 16, 80, true >(tid,       wrow, xsh, bsh, w3s, osh);
    } else if (tid < 128) {
        path_fn< 8, 16,  4, 1, 5, 5, 15872,  -1, 143,   0, 40, 80, false>(tid - 64,  wrow, xsh, bsh, w3s, osh);
    } else if (tid < 192) {
        path_fn< 8,  4, 16, 5, 1, 5, 16896,  -1, 213,  40,  0, 80, false>(tid - 128, wrow, xsh, bsh, w3s, osh);
    } else if (tid < 224) {
        path_fn<16,  8,  4, 3, 5, 3, 14848,  -1,  53,  16, 40, 32, false>(tid - 192, wrow, xsh, bsh, w3s, osh);
    } else if (tid < 256) {
        path_fn<16,  4,  8, 5, 3, 3, 15360,  -1,  98,  40, 16, 32, false>(tid - 224, wrow, xsh, bsh, w3s, osh);
    } else if (tid < 272) {
        path_fn<32,  4,  4, 5, 5, 1, 10240, 320,  10,  40, 40,  0, false>(tid - 256, wrow, xsh, bsh, w3s, osh);
        path_fn< 8,  4,  4, 5, 5, 5, 17408,  -1, 238,  40, 40, 80, true >(tid - 256, wrow, xsh, bsh, w3s, osh);
    }
    __syncthreads();

    for (int i = tid; i < OUTD * OUTD; i += ETHREADS)
        out[(size_t)n * (OUTD * OUTD) + i] = osh[i];
}

// ---------------- launch ----------------
extern "C" void kernel_launch(void* const* d_in, const int* in_sizes, int n_in,
                              void* d_out, int out_size) {
    const float* x_in  = (const float*)d_in[0];
    const float* embed = (const float*)d_in[1];
    const float* w1w   = (const float*)d_in[2];
    const float* b1w   = (const float*)d_in[3];
    const float* w2w   = (const float*)d_in[4];
    const float* b2w   = (const float*)d_in[5];
    const float* w1b   = (const float*)d_in[6];
    const float* b1b   = (const float*)d_in[7];
    const float* w2b   = (const float*)d_in[8];
    const float* b2b   = (const float*)d_in[9];
    float* out = (float*)d_out;

    cudaFuncSetAttribute(gemm_mma_kernel, cudaFuncAttributeMaxDynamicSharedMemorySize, GM_SMEM_TOT);

    w3j_init_kernel<<<1, 384>>>();
    hidden_kernel<<<NN / HNODES, 128>>>(embed, w1w, b1w, w1b, b1b);
    bias_kernel<<<NN / BNODES, 352>>>(w2b, b2b);
    gemm_mma_kernel<<<dim3(NPW / 128, NN / 128), 256, GM_SMEM_TOT>>>(w2w, b2w);
    expand_kernel<<<NN, ETHREADS>>>(x_in, out);
}